// round 14
// baseline (speedup 1.0000x reference)
#include <cuda_runtime.h>
#include <cuda_fp16.h>
#include <cstdint>

// Problem constants
#define NN 100000      // nodes
#define NE 3200000     // edges
#define NF 512         // in features
#define NH 256         // hidden
#define NL 64          // latent

// ---------------------------------------------------------------------------
// Scratch (device globals -> allocation-free, graph-capturable)
// ---------------------------------------------------------------------------
__device__ __half g_xh [(size_t)NN * NF];   // x in fp16 [NN,512]
__device__ __half g_xwh[(size_t)NN * NH];   // GEMM1 out [NN,256]; reused as GEMM2 out [NN,128]
__device__ __half g_h  [(size_t)NN * NH];   // relu(spmm1) fp16 [NN,256]
__device__ __half g_B1 [(size_t)256 * 512]; // W1^T fp16  [N=256, K=512]
__device__ __half g_B2 [(size_t)128 * 256]; // [Wmu|Wlv]^T fp16 [N=128, K=256]
__device__ int   g_off[NN + 1];
__device__ int   g_deg[NN];
__device__ int   g_cur[NN];
__device__ int2  g_edge[NE];                // .x = src, .y = bits(weight), sorted by dst

// ---------------------------------------------------------------------------
// Streams/events for graph-forked overlap (created at load time)
// ---------------------------------------------------------------------------
struct OverlapRes {
    cudaStream_t s2 = nullptr;
    cudaEvent_t  eFork = nullptr, eJoin = nullptr;
    bool ok = false;
    OverlapRes() {
        ok = (cudaStreamCreateWithFlags(&s2, cudaStreamNonBlocking) == cudaSuccess) &&
             (cudaEventCreateWithFlags(&eFork, cudaEventDisableTiming) == cudaSuccess) &&
             (cudaEventCreateWithFlags(&eJoin, cudaEventDisableTiming) == cudaSuccess);
    }
};
static OverlapRes g_ov;

// ---------------------------------------------------------------------------
// PTX helpers
// ---------------------------------------------------------------------------
__device__ __forceinline__ uint32_t smem_u32(const void* p) {
    uint32_t a;
    asm("{ .reg .u64 t; cvta.to.shared.u64 t, %1; cvt.u32.u64 %0, t; }" : "=r"(a) : "l"(p));
    return a;
}
__device__ __forceinline__ void cp16(uint32_t dst, const void* src, int sz) {
    asm volatile("cp.async.cg.shared.global [%0], [%1], 16, %2;"
                 :: "r"(dst), "l"(src), "r"(sz) : "memory");
}
__device__ __forceinline__ void cp_commit() {
    asm volatile("cp.async.commit_group;" ::: "memory");
}
template<int N> __device__ __forceinline__ void cp_wait() {
    asm volatile("cp.async.wait_group %0;" :: "n"(N) : "memory");
}

// ---------------------------------------------------------------------------
// CSR build
// ---------------------------------------------------------------------------
__global__ void k_zero_deg() {
    int i = blockIdx.x * blockDim.x + threadIdx.x;
    if (i < NN) g_deg[i] = 0;
}
__global__ void k_hist(const int* __restrict__ ei) {
    int e = blockIdx.x * blockDim.x + threadIdx.x;
    if (e < NE) atomicAdd(&g_deg[__ldg(ei + NE + e)], 1);
}
__global__ void k_scan() {
    __shared__ int wsum[32];
    int tid = threadIdx.x, lane = tid & 31, wid = tid >> 5;
    int carry = 0;
    for (int base = 0; base < NN; base += 1024) {
        int i = base + tid;
        int v = (i < NN) ? g_deg[i] : 0;
        int x = v;
        #pragma unroll
        for (int o = 1; o < 32; o <<= 1) {
            int y = __shfl_up_sync(0xffffffffu, x, o);
            if (lane >= o) x += y;
        }
        if (lane == 31) wsum[wid] = x;
        __syncthreads();
        if (wid == 0) {
            int s = wsum[lane];
            #pragma unroll
            for (int o = 1; o < 32; o <<= 1) {
                int y = __shfl_up_sync(0xffffffffu, s, o);
                if (lane >= o) s += y;
            }
            wsum[lane] = s;
        }
        __syncthreads();
        int excl = carry + x - v + (wid ? wsum[wid - 1] : 0);
        if (i < NN) { g_off[i] = excl; g_cur[i] = excl; }
        carry += wsum[31];
        __syncthreads();
    }
    if (tid == 0) g_off[NN] = carry;
}
__global__ void k_scatter(const int* __restrict__ ei, const float* __restrict__ ew) {
    int e = blockIdx.x * blockDim.x + threadIdx.x;
    if (e < NE) {
        int src = __ldg(ei + e);
        int dst = __ldg(ei + NE + e);
        float w = __ldg(ew + e);
        int pos = atomicAdd(&g_cur[dst], 1);
        g_edge[pos] = make_int2(src, __float_as_int(w));
    }
}

// ---------------------------------------------------------------------------
// fp16 prep
// ---------------------------------------------------------------------------
__global__ __launch_bounds__(256) void k_conv_x(const float* __restrict__ x) {
    int t = blockIdx.x * blockDim.x + threadIdx.x;   // one float4 -> half4
    if (t >= NN * 128) return;
    float4 v = ((const float4*)x)[t];
    __half2 h0 = __float22half2_rn(make_float2(v.x, v.y));
    __half2 h1 = __float22half2_rn(make_float2(v.z, v.w));
    ((__half2*)g_xh)[t * 2]     = h0;
    ((__half2*)g_xh)[t * 2 + 1] = h1;
}
__global__ __launch_bounds__(256) void k_prepB1(const float* __restrict__ W1) {
    int t = blockIdx.x * blockDim.x + threadIdx.x;
    if (t >= 256 * 512) return;
    int n = t >> 9, k = t & 511;
    g_B1[t] = __float2half_rn(W1[(size_t)k * 256 + n]);
}
__global__ __launch_bounds__(256) void k_prepB2(const float* __restrict__ Wmu,
                                                const float* __restrict__ Wlv) {
    int t = blockIdx.x * blockDim.x + threadIdx.x;
    if (t >= 128 * 256) return;
    int n = t >> 8, k = t & 255;
    float w = (n < 64) ? Wmu[(size_t)k * 64 + n] : Wlv[(size_t)k * 64 + (n - 64)];
    g_B2[t] = __float2half_rn(w);
}

// ---------------------------------------------------------------------------
// fp16 mma.sync GEMM: C[128x128 tile] = A @ B^T, fp16 in, f32 acc, fp16 out
//   A: [M, KA] row-major fp16; B: [N, KA] K-contig fp16; CCH chunks of K=32
// ---------------------------------------------------------------------------
template<int CCH, int KA, int LDC>
__global__ __launch_bounds__(256) void k_mma(const __half* __restrict__ A,
                                             const __half* __restrict__ B,
                                             __half* __restrict__ C, int M)
{
    constexpr int LDS = 40;
    __shared__ __align__(16) __half As[2][128 * LDS];
    __shared__ __align__(16) __half Bs[2][128 * LDS];

    int tid = threadIdx.x, lane = tid & 31, wid = tid >> 5;
    int m0 = blockIdx.y * 128, n0 = blockIdx.x * 128;
    int wm = (wid >> 2) * 64, wn = (wid & 3) * 32;

    float acc[4][4][4];
    #pragma unroll
    for (int a = 0; a < 4; a++)
        #pragma unroll
        for (int b = 0; b < 4; b++)
            #pragma unroll
            for (int q = 0; q < 4; q++) acc[a][b][q] = 0.f;

    uint32_t aBase = smem_u32(As), bBase = smem_u32(Bs);
    int r_ld = tid >> 1;
    int s0_ld = (tid & 1) * 2;

    auto load = [&](int c, int st) {
        int k0 = c * 32;
        const __half* Ap = A + (size_t)(m0 + r_ld) * KA + k0;
        const __half* Bp = B + (size_t)(n0 + r_ld) * KA + k0;
        int sz = (m0 + r_ld < M) ? 16 : 0;
        uint32_t ad = aBase + (uint32_t)(st * 128 * LDS + r_ld * LDS) * 2;
        uint32_t bd = bBase + (uint32_t)(st * 128 * LDS + r_ld * LDS) * 2;
        #pragma unroll
        for (int i = 0; i < 2; i++) {
            int s = s0_ld + i;
            cp16(ad + s * 16, Ap + s * 8, sz);
            cp16(bd + s * 16, Bp + s * 8, 16);
        }
        cp_commit();
    };

    load(0, 0);
    for (int c = 0; c < CCH; c++) {
        int st = c & 1;
        if (c + 1 < CCH) { load(c + 1, st ^ 1); cp_wait<1>(); }
        else             { cp_wait<0>(); }
        __syncthreads();

        #pragma unroll
        for (int ks = 0; ks < 2; ks++) {
            uint32_t ra[4][4], rb[4][2];
            #pragma unroll
            for (int mi = 0; mi < 4; mi++) {
                int row = wm + mi * 16 + (lane & 15);
                int col = ks * 16 + (lane >> 4) * 8;
                uint32_t ad = aBase + (uint32_t)(st * 128 * LDS + row * LDS + col) * 2;
                asm volatile("ldmatrix.sync.aligned.m8n8.x4.shared.b16 {%0,%1,%2,%3}, [%4];"
                    : "=r"(ra[mi][0]), "=r"(ra[mi][1]), "=r"(ra[mi][2]), "=r"(ra[mi][3])
                    : "r"(ad));
            }
            #pragma unroll
            for (int ni = 0; ni < 4; ni++) {
                int row = wn + ni * 8 + (lane & 7);
                int col = ks * 16 + ((lane >> 3) & 1) * 8;
                uint32_t bd = bBase + (uint32_t)(st * 128 * LDS + row * LDS + col) * 2;
                asm volatile("ldmatrix.sync.aligned.m8n8.x2.shared.b16 {%0,%1}, [%2];"
                    : "=r"(rb[ni][0]), "=r"(rb[ni][1]) : "r"(bd));
            }
            #pragma unroll
            for (int mi = 0; mi < 4; mi++)
                #pragma unroll
                for (int ni = 0; ni < 4; ni++)
                    asm volatile(
                        "mma.sync.aligned.m16n8k16.row.col.f32.f16.f16.f32 "
                        "{%0,%1,%2,%3}, {%4,%5,%6,%7}, {%8,%9}, {%0,%1,%2,%3};"
                        : "+f"(acc[mi][ni][0]), "+f"(acc[mi][ni][1]),
                          "+f"(acc[mi][ni][2]), "+f"(acc[mi][ni][3])
                        : "r"(ra[mi][0]), "r"(ra[mi][1]), "r"(ra[mi][2]), "r"(ra[mi][3]),
                          "r"(rb[ni][0]), "r"(rb[ni][1]));
        }
        __syncthreads();
    }

    #pragma unroll
    for (int mi = 0; mi < 4; mi++) {
        int r0 = m0 + wm + mi * 16 + (lane >> 2);
        #pragma unroll
        for (int ni = 0; ni < 4; ni++) {
            int cc = n0 + wn + ni * 8 + (lane & 3) * 2;
            if (r0 < M)
                *(__half2*)(C + (size_t)r0 * LDC + cc) =
                    __float22half2_rn(make_float2(acc[mi][ni][0], acc[mi][ni][1]));
            if (r0 + 8 < M)
                *(__half2*)(C + (size_t)(r0 + 8) * LDC + cc) =
                    __float22half2_rn(make_float2(acc[mi][ni][2], acc[mi][ni][3]));
        }
    }
}

// ---------------------------------------------------------------------------
// SPMM1: h = relu(A @ xwh + b1), fp16 gather (16B/lane/edge), f32 acc,
// 2x-unrolled, fp16 out; warp/row. Streaming hints: edges __ldcs, output __stcs
// (protects g_xwh L2 residency).
// ---------------------------------------------------------------------------
__global__ __launch_bounds__(256) void k_spmm1(const float* __restrict__ b1) {
    int w    = (blockIdx.x * blockDim.x + threadIdx.x) >> 5;
    int lane = threadIdx.x & 31;
    if (w >= NN) return;

    int s0 = g_off[w], s1 = g_off[w + 1];
    float acc[8];
    #pragma unroll
    for (int i = 0; i < 8; i++) acc[i] = 0.f;

    auto addEdge = [&](int2 ed) {
        float we = __int_as_float(ed.y);
        uint4 v = __ldg((const uint4*)(g_xwh + (size_t)ed.x * NH) + lane);
        const __half2* hp = (const __half2*)&v;
        #pragma unroll
        for (int q = 0; q < 4; q++) {
            float2 f = __half22float2(hp[q]);
            acc[2*q]     = fmaf(we, f.x, acc[2*q]);
            acc[2*q + 1] = fmaf(we, f.y, acc[2*q + 1]);
        }
    };

    int e = s0;
    for (; e + 2 <= s1; e += 2) {
        int2 e0 = __ldcs(&g_edge[e]);
        int2 e1 = __ldcs(&g_edge[e + 1]);
        addEdge(e0); addEdge(e1);
    }
    if (e < s1) addEdge(__ldcs(&g_edge[e]));

    const float4* bb = (const float4*)(b1 + lane * 8);
    float4 b0 = __ldg(bb), b1v = __ldg(bb + 1);
    acc[0] = fmaxf(acc[0] + b0.x, 0.f);  acc[1] = fmaxf(acc[1] + b0.y, 0.f);
    acc[2] = fmaxf(acc[2] + b0.z, 0.f);  acc[3] = fmaxf(acc[3] + b0.w, 0.f);
    acc[4] = fmaxf(acc[4] + b1v.x, 0.f); acc[5] = fmaxf(acc[5] + b1v.y, 0.f);
    acc[6] = fmaxf(acc[6] + b1v.z, 0.f); acc[7] = fmaxf(acc[7] + b1v.w, 0.f);

    __half2 hv[4];
    #pragma unroll
    for (int q = 0; q < 4; q++)
        hv[q] = __float22half2_rn(make_float2(acc[2*q], acc[2*q + 1]));
    __stcs((uint4*)(g_h + (size_t)w * NH + lane * 8), *(uint4*)hv);
}

// ---------------------------------------------------------------------------
// SPMM2: D=128 fp16 gather from g_xwh (8B/lane/edge), f32 acc, 2x unroll,
// bias, final f32 out. Streaming hints on edges + output.
// ---------------------------------------------------------------------------
__global__ __launch_bounds__(256) void k_spmm2(
    const float* __restrict__ bmu, const float* __restrict__ blv,
    float* __restrict__ out)
{
    int w    = (blockIdx.x * blockDim.x + threadIdx.x) >> 5;
    int lane = threadIdx.x & 31;
    if (w >= NN) return;

    int s0 = g_off[w], s1 = g_off[w + 1];
    float acc[4] = {0.f, 0.f, 0.f, 0.f};

    auto addEdge = [&](int2 ed) {
        float we = __int_as_float(ed.y);
        uint2 v = __ldg((const uint2*)(g_xwh + (size_t)ed.x * 128) + lane);
        float2 f0 = __half22float2(*(const __half2*)&v.x);
        float2 f1 = __half22float2(*(const __half2*)&v.y);
        acc[0] = fmaf(we, f0.x, acc[0]);
        acc[1] = fmaf(we, f0.y, acc[1]);
        acc[2] = fmaf(we, f1.x, acc[2]);
        acc[3] = fmaf(we, f1.y, acc[3]);
    };

    int e = s0;
    for (; e + 2 <= s1; e += 2) {
        int2 e0 = __ldcs(&g_edge[e]);
        int2 e1 = __ldcs(&g_edge[e + 1]);
        addEdge(e0); addEdge(e1);
    }
    if (e < s1) addEdge(__ldcs(&g_edge[e]));

    int col = lane * 4;
    if (col < 64) {
        float4 b = __ldg((const float4*)(bmu + col));
        __stcs((float4*)(out + (size_t)w * 64 + col),
               make_float4(acc[0] + b.x, acc[1] + b.y, acc[2] + b.z, acc[3] + b.w));
    } else {
        int jc = col - 64;
        float4 b = __ldg((const float4*)(blv + jc));
        __stcs((float4*)(out + (size_t)NN * 64 + (size_t)w * 64 + jc),
               make_float4(acc[0] + b.x, acc[1] + b.y, acc[2] + b.z, acc[3] + b.w));
    }
}

// ---------------------------------------------------------------------------
// Launch (round-13 schedule; conv_x first on the dense stream)
// ---------------------------------------------------------------------------
extern "C" void kernel_launch(void* const* d_in, const int* in_sizes, int n_in,
                              void* d_out, int out_size)
{
    const float* x   = (const float*)d_in[0];
    const int*   ei  = (const int*)  d_in[1];
    const float* ew  = (const float*)d_in[2];
    const float* W1  = (const float*)d_in[3];
    const float* b1  = (const float*)d_in[4];
    const float* Wmu = (const float*)d_in[5];
    const float* bmu = (const float*)d_in[6];
    const float* Wlv = (const float*)d_in[7];
    const float* blv = (const float*)d_in[8];
    float* out = (float*)d_out;

    __half *p_xh, *p_xwh, *p_h, *p_B1, *p_B2;
    cudaGetSymbolAddress((void**)&p_xh,  g_xh);
    cudaGetSymbolAddress((void**)&p_xwh, g_xwh);
    cudaGetSymbolAddress((void**)&p_h,   g_h);
    cudaGetSymbolAddress((void**)&p_B1,  g_B1);
    cudaGetSymbolAddress((void**)&p_B2,  g_B2);

    bool fork = g_ov.ok;
    cudaStream_t sC = fork ? g_ov.s2 : (cudaStream_t)0;

    if (fork) {
        cudaEventRecord(g_ov.eFork, 0);
        cudaStreamWaitEvent(g_ov.s2, g_ov.eFork, 0);
    }

    // CSR by dst (stream sC — overlaps dense chain)
    k_zero_deg<<<(NN + 255) / 256, 256, 0, sC>>>();
    k_hist    <<<(NE + 255) / 256, 256, 0, sC>>>(ei);
    k_scan    <<<1, 1024, 0, sC>>>();
    k_scatter <<<(NE + 255) / 256, 256, 0, sC>>>(ei, ew);
    if (fork) cudaEventRecord(g_ov.eJoin, g_ov.s2);

    // Dense chain (stream 0): conv first, then tiny weight preps, then GEMM1
    k_conv_x<<<(NN * 128 + 255) / 256, 256>>>(x);
    k_prepB1<<<(256 * 512 + 255) / 256, 256>>>(W1);
    k_prepB2<<<(128 * 256 + 255) / 256, 256>>>(Wmu, Wlv);
    {
        dim3 grid(2, (NN + 127) / 128);
        k_mma<16, 512, 256><<<grid, 256>>>(p_xh, p_B1, p_xwh, NN);
    }

    if (fork) cudaStreamWaitEvent(0, g_ov.eJoin, 0);

    // SPMM1 + bias + relu
    k_spmm1<<<(NN + 7) / 8, 256>>>(b1);

    // GEMM2: [mu|logvar] = h @ [Wmu|Wlv]  (K=256), in-place into g_xwh
    {
        dim3 grid(1, (NN + 127) / 128);
        k_mma<8, 256, 128><<<grid, 256>>>(p_h, p_B2, p_xwh, NN);
    }

    // SPMM2 + bias -> d_out
    k_spmm2<<<(NN + 7) / 8, 256>>>(bmu, blv, out);
}

// round 16
// speedup vs baseline: 1.0103x; 1.0103x over previous
#include <cuda_runtime.h>
#include <cuda_fp16.h>
#include <cstdint>

// Problem constants
#define NN 100000      // nodes
#define NE 3200000     // edges
#define NF 512         // in features
#define NH 256         // hidden
#define NL 64          // latent

// ---------------------------------------------------------------------------
// Scratch (device globals -> allocation-free, graph-capturable)
// ---------------------------------------------------------------------------
__device__ __half g_xh [(size_t)NN * NF];   // x in fp16 [NN,512]
__device__ __half g_xwh[(size_t)NN * NH];   // GEMM1 out [NN,256]; reused as GEMM2 out [NN,128]
__device__ __half g_h  [(size_t)NN * NH];   // relu(spmm1) fp16 [NN,256]
__device__ __half g_B1 [(size_t)256 * 512]; // W1^T fp16  [N=256, K=512]
__device__ __half g_B2 [(size_t)128 * 256]; // [Wmu|Wlv]^T fp16 [N=128, K=256]
__device__ int   g_off[NN + 1];
__device__ int   g_deg[NN];
__device__ int   g_cur[NN];
__device__ int2  g_edge[NE];                // .x = src, .y = bits(weight), sorted by dst

// ---------------------------------------------------------------------------
// Streams/events for graph-forked overlap (created at load time)
// ---------------------------------------------------------------------------
struct OverlapRes {
    cudaStream_t s2 = nullptr;
    cudaEvent_t  eFork = nullptr, eJoin = nullptr;
    bool ok = false;
    OverlapRes() {
        ok = (cudaStreamCreateWithFlags(&s2, cudaStreamNonBlocking) == cudaSuccess) &&
             (cudaEventCreateWithFlags(&eFork, cudaEventDisableTiming) == cudaSuccess) &&
             (cudaEventCreateWithFlags(&eJoin, cudaEventDisableTiming) == cudaSuccess);
    }
};
static OverlapRes g_ov;

// ---------------------------------------------------------------------------
// PTX helpers
// ---------------------------------------------------------------------------
__device__ __forceinline__ uint32_t smem_u32(const void* p) {
    uint32_t a;
    asm("{ .reg .u64 t; cvta.to.shared.u64 t, %1; cvt.u32.u64 %0, t; }" : "=r"(a) : "l"(p));
    return a;
}
__device__ __forceinline__ void cp16(uint32_t dst, const void* src, int sz) {
    asm volatile("cp.async.cg.shared.global [%0], [%1], 16, %2;"
                 :: "r"(dst), "l"(src), "r"(sz) : "memory");
}
__device__ __forceinline__ void cp_commit() {
    asm volatile("cp.async.commit_group;" ::: "memory");
}
template<int N> __device__ __forceinline__ void cp_wait() {
    asm volatile("cp.async.wait_group %0;" :: "n"(N) : "memory");
}

// ---------------------------------------------------------------------------
// CSR build
// ---------------------------------------------------------------------------
__global__ void k_zero_deg() {
    int i = blockIdx.x * blockDim.x + threadIdx.x;
    if (i < NN) g_deg[i] = 0;
}
__global__ void k_hist(const int* __restrict__ ei) {
    int e = blockIdx.x * blockDim.x + threadIdx.x;
    if (e < NE) atomicAdd(&g_deg[__ldg(ei + NE + e)], 1);
}
__global__ void k_scan() {
    __shared__ int wsum[32];
    int tid = threadIdx.x, lane = tid & 31, wid = tid >> 5;
    int carry = 0;
    for (int base = 0; base < NN; base += 1024) {
        int i = base + tid;
        int v = (i < NN) ? g_deg[i] : 0;
        int x = v;
        #pragma unroll
        for (int o = 1; o < 32; o <<= 1) {
            int y = __shfl_up_sync(0xffffffffu, x, o);
            if (lane >= o) x += y;
        }
        if (lane == 31) wsum[wid] = x;
        __syncthreads();
        if (wid == 0) {
            int s = wsum[lane];
            #pragma unroll
            for (int o = 1; o < 32; o <<= 1) {
                int y = __shfl_up_sync(0xffffffffu, s, o);
                if (lane >= o) s += y;
            }
            wsum[lane] = s;
        }
        __syncthreads();
        int excl = carry + x - v + (wid ? wsum[wid - 1] : 0);
        if (i < NN) { g_off[i] = excl; g_cur[i] = excl; }
        carry += wsum[31];
        __syncthreads();
    }
    if (tid == 0) g_off[NN] = carry;
}
__global__ void k_scatter(const int* __restrict__ ei, const float* __restrict__ ew) {
    int e = blockIdx.x * blockDim.x + threadIdx.x;
    if (e < NE) {
        int src = __ldg(ei + e);
        int dst = __ldg(ei + NE + e);
        float w = __ldg(ew + e);
        int pos = atomicAdd(&g_cur[dst], 1);
        g_edge[pos] = make_int2(src, __float_as_int(w));
    }
}

// ---------------------------------------------------------------------------
// fp16 prep
// ---------------------------------------------------------------------------
__global__ __launch_bounds__(256) void k_conv_x(const float* __restrict__ x) {
    int t = blockIdx.x * blockDim.x + threadIdx.x;   // one float4 -> half4
    if (t >= NN * 128) return;
    float4 v = ((const float4*)x)[t];
    __half2 h0 = __float22half2_rn(make_float2(v.x, v.y));
    __half2 h1 = __float22half2_rn(make_float2(v.z, v.w));
    ((__half2*)g_xh)[t * 2]     = h0;
    ((__half2*)g_xh)[t * 2 + 1] = h1;
}
__global__ __launch_bounds__(256) void k_prepB1(const float* __restrict__ W1) {
    int t = blockIdx.x * blockDim.x + threadIdx.x;
    if (t >= 256 * 512) return;
    int n = t >> 9, k = t & 511;
    g_B1[t] = __float2half_rn(W1[(size_t)k * 256 + n]);
}
__global__ __launch_bounds__(256) void k_prepB2(const float* __restrict__ Wmu,
                                                const float* __restrict__ Wlv) {
    int t = blockIdx.x * blockDim.x + threadIdx.x;
    if (t >= 128 * 256) return;
    int n = t >> 8, k = t & 255;
    float w = (n < 64) ? Wmu[(size_t)k * 64 + n] : Wlv[(size_t)k * 64 + (n - 64)];
    g_B2[t] = __float2half_rn(w);
}

// ---------------------------------------------------------------------------
// fp16 mma.sync GEMM: C[128x128 tile] = A @ B^T, fp16 in, f32 acc, fp16 out
//   A: [M, KA] row-major fp16; B: [N, KA] K-contig fp16; CCH chunks of K=32
// ---------------------------------------------------------------------------
template<int CCH, int KA, int LDC>
__global__ __launch_bounds__(256) void k_mma(const __half* __restrict__ A,
                                             const __half* __restrict__ B,
                                             __half* __restrict__ C, int M)
{
    constexpr int LDS = 40;
    __shared__ __align__(16) __half As[2][128 * LDS];
    __shared__ __align__(16) __half Bs[2][128 * LDS];

    int tid = threadIdx.x, lane = tid & 31, wid = tid >> 5;
    int m0 = blockIdx.y * 128, n0 = blockIdx.x * 128;
    int wm = (wid >> 2) * 64, wn = (wid & 3) * 32;

    float acc[4][4][4];
    #pragma unroll
    for (int a = 0; a < 4; a++)
        #pragma unroll
        for (int b = 0; b < 4; b++)
            #pragma unroll
            for (int q = 0; q < 4; q++) acc[a][b][q] = 0.f;

    uint32_t aBase = smem_u32(As), bBase = smem_u32(Bs);
    int r_ld = tid >> 1;
    int s0_ld = (tid & 1) * 2;

    auto load = [&](int c, int st) {
        int k0 = c * 32;
        const __half* Ap = A + (size_t)(m0 + r_ld) * KA + k0;
        const __half* Bp = B + (size_t)(n0 + r_ld) * KA + k0;
        int sz = (m0 + r_ld < M) ? 16 : 0;
        uint32_t ad = aBase + (uint32_t)(st * 128 * LDS + r_ld * LDS) * 2;
        uint32_t bd = bBase + (uint32_t)(st * 128 * LDS + r_ld * LDS) * 2;
        #pragma unroll
        for (int i = 0; i < 2; i++) {
            int s = s0_ld + i;
            cp16(ad + s * 16, Ap + s * 8, sz);
            cp16(bd + s * 16, Bp + s * 8, 16);
        }
        cp_commit();
    };

    load(0, 0);
    for (int c = 0; c < CCH; c++) {
        int st = c & 1;
        if (c + 1 < CCH) { load(c + 1, st ^ 1); cp_wait<1>(); }
        else             { cp_wait<0>(); }
        __syncthreads();

        #pragma unroll
        for (int ks = 0; ks < 2; ks++) {
            uint32_t ra[4][4], rb[4][2];
            #pragma unroll
            for (int mi = 0; mi < 4; mi++) {
                int row = wm + mi * 16 + (lane & 15);
                int col = ks * 16 + (lane >> 4) * 8;
                uint32_t ad = aBase + (uint32_t)(st * 128 * LDS + row * LDS + col) * 2;
                asm volatile("ldmatrix.sync.aligned.m8n8.x4.shared.b16 {%0,%1,%2,%3}, [%4];"
                    : "=r"(ra[mi][0]), "=r"(ra[mi][1]), "=r"(ra[mi][2]), "=r"(ra[mi][3])
                    : "r"(ad));
            }
            #pragma unroll
            for (int ni = 0; ni < 4; ni++) {
                int row = wn + ni * 8 + (lane & 7);
                int col = ks * 16 + ((lane >> 3) & 1) * 8;
                uint32_t bd = bBase + (uint32_t)(st * 128 * LDS + row * LDS + col) * 2;
                asm volatile("ldmatrix.sync.aligned.m8n8.x2.shared.b16 {%0,%1}, [%2];"
                    : "=r"(rb[ni][0]), "=r"(rb[ni][1]) : "r"(bd));
            }
            #pragma unroll
            for (int mi = 0; mi < 4; mi++)
                #pragma unroll
                for (int ni = 0; ni < 4; ni++)
                    asm volatile(
                        "mma.sync.aligned.m16n8k16.row.col.f32.f16.f16.f32 "
                        "{%0,%1,%2,%3}, {%4,%5,%6,%7}, {%8,%9}, {%0,%1,%2,%3};"
                        : "+f"(acc[mi][ni][0]), "+f"(acc[mi][ni][1]),
                          "+f"(acc[mi][ni][2]), "+f"(acc[mi][ni][3])
                        : "r"(ra[mi][0]), "r"(ra[mi][1]), "r"(ra[mi][2]), "r"(ra[mi][3]),
                          "r"(rb[ni][0]), "r"(rb[ni][1]));
        }
        __syncthreads();
    }

    #pragma unroll
    for (int mi = 0; mi < 4; mi++) {
        int r0 = m0 + wm + mi * 16 + (lane >> 2);
        #pragma unroll
        for (int ni = 0; ni < 4; ni++) {
            int cc = n0 + wn + ni * 8 + (lane & 3) * 2;
            if (r0 < M)
                *(__half2*)(C + (size_t)r0 * LDC + cc) =
                    __float22half2_rn(make_float2(acc[mi][ni][0], acc[mi][ni][1]));
            if (r0 + 8 < M)
                *(__half2*)(C + (size_t)(r0 + 8) * LDC + cc) =
                    __float22half2_rn(make_float2(acc[mi][ni][2], acc[mi][ni][3]));
        }
    }
}

// ---------------------------------------------------------------------------
// SPMM1: h = relu(A @ xwh + b1), fp16 gather (16B/lane/edge), f32 acc,
// 2x-unrolled, fp16 out; warp/row
// ---------------------------------------------------------------------------
__global__ __launch_bounds__(256) void k_spmm1(const float* __restrict__ b1) {
    int w    = (blockIdx.x * blockDim.x + threadIdx.x) >> 5;
    int lane = threadIdx.x & 31;
    if (w >= NN) return;

    int s0 = g_off[w], s1 = g_off[w + 1];
    float acc[8];
    #pragma unroll
    for (int i = 0; i < 8; i++) acc[i] = 0.f;

    auto addEdge = [&](int2 ed) {
        float we = __int_as_float(ed.y);
        uint4 v = __ldg((const uint4*)(g_xwh + (size_t)ed.x * NH) + lane);
        const __half2* hp = (const __half2*)&v;
        #pragma unroll
        for (int q = 0; q < 4; q++) {
            float2 f = __half22float2(hp[q]);
            acc[2*q]     = fmaf(we, f.x, acc[2*q]);
            acc[2*q + 1] = fmaf(we, f.y, acc[2*q + 1]);
        }
    };

    int e = s0;
    for (; e + 2 <= s1; e += 2) { addEdge(g_edge[e]); addEdge(g_edge[e + 1]); }
    if (e < s1) addEdge(g_edge[e]);

    const float4* bb = (const float4*)(b1 + lane * 8);
    float4 b0 = __ldg(bb), b1v = __ldg(bb + 1);
    acc[0] = fmaxf(acc[0] + b0.x, 0.f);  acc[1] = fmaxf(acc[1] + b0.y, 0.f);
    acc[2] = fmaxf(acc[2] + b0.z, 0.f);  acc[3] = fmaxf(acc[3] + b0.w, 0.f);
    acc[4] = fmaxf(acc[4] + b1v.x, 0.f); acc[5] = fmaxf(acc[5] + b1v.y, 0.f);
    acc[6] = fmaxf(acc[6] + b1v.z, 0.f); acc[7] = fmaxf(acc[7] + b1v.w, 0.f);

    __half2 hv[4];
    #pragma unroll
    for (int q = 0; q < 4; q++)
        hv[q] = __float22half2_rn(make_float2(acc[2*q], acc[2*q + 1]));
    *(uint4*)(g_h + (size_t)w * NH + lane * 8) = *(uint4*)hv;
}

// ---------------------------------------------------------------------------
// SPMM2: D=128 fp16 gather from g_xwh (8B/lane/edge), f32 acc, 2x unroll,
// bias, final f32 out. (g_xwh reused as GEMM2 out; serial schedule = safe.)
// ---------------------------------------------------------------------------
__global__ __launch_bounds__(256) void k_spmm2(
    const float* __restrict__ bmu, const float* __restrict__ blv,
    float* __restrict__ out)
{
    int w    = (blockIdx.x * blockDim.x + threadIdx.x) >> 5;
    int lane = threadIdx.x & 31;
    if (w >= NN) return;

    int s0 = g_off[w], s1 = g_off[w + 1];
    float acc[4] = {0.f, 0.f, 0.f, 0.f};

    auto addEdge = [&](int2 ed) {
        float we = __int_as_float(ed.y);
        uint2 v = __ldg((const uint2*)(g_xwh + (size_t)ed.x * 128) + lane);
        float2 f0 = __half22float2(*(const __half2*)&v.x);
        float2 f1 = __half22float2(*(const __half2*)&v.y);
        acc[0] = fmaf(we, f0.x, acc[0]);
        acc[1] = fmaf(we, f0.y, acc[1]);
        acc[2] = fmaf(we, f1.x, acc[2]);
        acc[3] = fmaf(we, f1.y, acc[3]);
    };

    int e = s0;
    for (; e + 2 <= s1; e += 2) { addEdge(g_edge[e]); addEdge(g_edge[e + 1]); }
    if (e < s1) addEdge(g_edge[e]);

    int col = lane * 4;
    if (col < 64) {
        float4 b = __ldg((const float4*)(bmu + col));
        *(float4*)(out + (size_t)w * 64 + col) =
            make_float4(acc[0] + b.x, acc[1] + b.y, acc[2] + b.z, acc[3] + b.w);
    } else {
        int jc = col - 64;
        float4 b = __ldg((const float4*)(blv + jc));
        *(float4*)(out + (size_t)NN * 64 + (size_t)w * 64 + jc) =
            make_float4(acc[0] + b.x, acc[1] + b.y, acc[2] + b.z, acc[3] + b.w);
    }
}

// ---------------------------------------------------------------------------
// Launch (round-13 schedule; conv_x first on the dense stream)
// ---------------------------------------------------------------------------
extern "C" void kernel_launch(void* const* d_in, const int* in_sizes, int n_in,
                              void* d_out, int out_size)
{
    const float* x   = (const float*)d_in[0];
    const int*   ei  = (const int*)  d_in[1];
    const float* ew  = (const float*)d_in[2];
    const float* W1  = (const float*)d_in[3];
    const float* b1  = (const float*)d_in[4];
    const float* Wmu = (const float*)d_in[5];
    const float* bmu = (const float*)d_in[6];
    const float* Wlv = (const float*)d_in[7];
    const float* blv = (const float*)d_in[8];
    float* out = (float*)d_out;

    __half *p_xh, *p_xwh, *p_h, *p_B1, *p_B2;
    cudaGetSymbolAddress((void**)&p_xh,  g_xh);
    cudaGetSymbolAddress((void**)&p_xwh, g_xwh);
    cudaGetSymbolAddress((void**)&p_h,   g_h);
    cudaGetSymbolAddress((void**)&p_B1,  g_B1);
    cudaGetSymbolAddress((void**)&p_B2,  g_B2);

    bool fork = g_ov.ok;
    cudaStream_t sC = fork ? g_ov.s2 : (cudaStream_t)0;

    if (fork) {
        cudaEventRecord(g_ov.eFork, 0);
        cudaStreamWaitEvent(g_ov.s2, g_ov.eFork, 0);
    }

    // CSR by dst (stream sC — overlaps dense chain)
    k_zero_deg<<<(NN + 255) / 256, 256, 0, sC>>>();
    k_hist    <<<(NE + 255) / 256, 256, 0, sC>>>(ei);
    k_scan    <<<1, 1024, 0, sC>>>();
    k_scatter <<<(NE + 255) / 256, 256, 0, sC>>>(ei, ew);
    if (fork) cudaEventRecord(g_ov.eJoin, g_ov.s2);

    // Dense chain (stream 0): conv first, then tiny weight preps, then GEMM1
    k_conv_x<<<(NN * 128 + 255) / 256, 256>>>(x);
    k_prepB1<<<(256 * 512 + 255) / 256, 256>>>(W1);
    k_prepB2<<<(128 * 256 + 255) / 256, 256>>>(Wmu, Wlv);
    {
        dim3 grid(2, (NN + 127) / 128);
        k_mma<16, 512, 256><<<grid, 256>>>(p_xh, p_B1, p_xwh, NN);
    }

    if (fork) cudaStreamWaitEvent(0, g_ov.eJoin, 0);

    // SPMM1 + bias + relu
    k_spmm1<<<(NN + 7) / 8, 256>>>(b1);

    // GEMM2: [mu|logvar] = h @ [Wmu|Wlv]  (K=256), in-place into g_xwh
    {
        dim3 grid(1, (NN + 127) / 128);
        k_mma<8, 256, 128><<<grid, 256>>>(p_h, p_B2, p_xwh, NN);
    }

    // SPMM2 + bias -> d_out
    k_spmm2<<<(NN + 7) / 8, 256>>>(bmu, blv, out);
}